// round 13
// baseline (speedup 1.0000x reference)
#include <cuda_runtime.h>
#include <cuda_bf16.h>

#define NSAMPLE 32
#define NPTS 4096
#define MAXB 8
#define BLOCK_THREADS 64
#define WARPS_PER_BLOCK (BLOCK_THREADS / 32)
#define SCR_SLOTS 192            // max slot overshoot: 31 + 128 = 159
#define RECS_PER_B (NPTS / 2)    // 2048 pair-records per batch

// Pair-record layout (32B per record, two float4s):
//   g_pk[2r]   = (x_n0, x_n1, y_n0, y_n1)
//   g_pk[2r+1] = (z_n0, z_n1, w_n0, w_n1)
// where record r (chunk-pair c = r>>5, lane l = r&31) covers points
// n0 = c*64 + l and n1 = n0 + 32. An LDG.128 of each half lands every f32x2
// operand (x0,x1), (y0,y1), (z0,z1), (w0,w1) in an ALIGNED register pair, so
// the pk2 movs fold away. +128 float4 pad for the depth-2-iteration prefetch
// overrun on the final iteration (loaded, never consumed).
__device__ float4 g_pk[2 * (MAXB * RECS_PER_B) + 128];

// ---- f32x2 helpers (sm_103a); arithmetic FROZEN from rounds 10/12
// (rel_err 7.915904e-4 with seed-deterministic inputs).
__device__ __forceinline__ unsigned long long pk2(float lo, float hi) {
    unsigned long long r;
    asm("mov.b64 %0, {%1, %2};" : "=l"(r) : "f"(lo), "f"(hi));
    return r;
}
__device__ __forceinline__ void upk2(unsigned long long v, float& lo, float& hi) {
    asm("mov.b64 {%0, %1}, %2;" : "=f"(lo), "=f"(hi) : "l"(v));
}
__device__ __forceinline__ unsigned long long mul2(unsigned long long a,
                                                   unsigned long long b) {
    unsigned long long r;
    asm("mul.rn.f32x2 %0, %1, %2;" : "=l"(r) : "l"(a), "l"(b));
    return r;
}
__device__ __forceinline__ unsigned long long add2(unsigned long long a,
                                                   unsigned long long b) {
    unsigned long long r;
    asm("add.rn.f32x2 %0, %1, %2;" : "=l"(r) : "l"(a), "l"(b));
    return r;
}

// Pre-pass: build pair-records. |p|^2 expression FROZEN:
// rn((rn(x*x) + rn(y*y)) + rn(z*z)), no FMA contraction.
__global__ void pack_kernel(const float* __restrict__ xyz, int total_recs) {
    const int j = blockIdx.x * blockDim.x + threadIdx.x;
    if (j >= total_recs) return;
    const int b = j / RECS_PER_B;
    const int s = j - b * RECS_PER_B;
    const int n0 = b * NPTS + ((s >> 5) << 6) + (s & 31);
    const int n1 = n0 + 32;

    const float x0 = xyz[n0 * 3 + 0], y0 = xyz[n0 * 3 + 1], z0 = xyz[n0 * 3 + 2];
    const float x1 = xyz[n1 * 3 + 0], y1 = xyz[n1 * 3 + 1], z1 = xyz[n1 * 3 + 2];
    const float w0 = __fadd_rn(__fadd_rn(__fmul_rn(x0, x0), __fmul_rn(y0, y0)),
                               __fmul_rn(z0, z0));
    const float w1 = __fadd_rn(__fadd_rn(__fmul_rn(x1, x1), __fmul_rn(y1, y1)),
                               __fmul_rn(z1, z1));
    g_pk[2 * j + 0] = make_float4(x0, x1, y0, y1);
    g_pk[2 * j + 1] = make_float4(z0, z1, w0, w1);
}

// One warp per query, 128 points/iter, R12's copy-then-prefetch skeleton
// (the explicit c=s copies are what let ptxas hoist the loads — R11 removed
// them and collapsed). Operands arrive pair-aligned from the record layout,
// so the pk2 movs fold into register allocation. All fp ops bit-identical to
// rounds 10/12. Ballot-ordered deferred smem emission; epilogue select does
// copy + truncate + pad-with-first in one coalesced store.
__global__ void ball_query_kernel(const float* __restrict__ xyz,
                                  float* __restrict__ out) {
    __shared__ float scr[WARPS_PER_BLOCK][SCR_SLOTS];

    const int lane = threadIdx.x & 31;
    const int w = threadIdx.x >> 5;
    const int gw = blockIdx.x * WARPS_PER_BLOCK + w;
    const int b = gw >> 12;          // / NPTS

    const float4* __restrict__ p = g_pk + 2 * ((size_t)b * RECS_PER_B + lane);

    // Query from xyz; qw uses the frozen |q|^2 expression.
    const float qx = xyz[gw * 3 + 0];
    const float qy = xyz[gw * 3 + 1];
    const float qz = xyz[gw * 3 + 2];
    const float qw = __fadd_rn(__fadd_rn(__fmul_rn(qx, qx), __fmul_rn(qy, qy)),
                               __fmul_rn(qz, qz));
    const unsigned long long qxp = pk2(qx, qx);
    const unsigned long long qyp = pk2(qy, qy);
    const unsigned long long qzp = pk2(qz, qz);
    const unsigned long long qwp = pk2(qw, qw);
    const unsigned long long M2  = pk2(-2.0f, -2.0f);

    const unsigned mlt = (1u << lane) - 1u;
    const float r2 = 0.04f;          // f32 promotion of 0.2*0.2
    int count = 0;

    // Prefetch iteration 0: chunk-pair 0 (A0,B0) and chunk-pair 1 (A1,B1).
    float4 a0 = p[0], b0 = p[1];     // points (lane, lane+32)
    float4 a1 = p[64], b1 = p[65];   // points (lane+64, lane+96)
    p += 128;                        // 64 records = 128 float4s per iter

    float f0 = (float)lane;          // emission values, +128.0f per iter
    float f1 = (float)(lane + 32);
    float f2 = (float)(lane + 64);
    float f3 = (float)(lane + 96);

    for (int it = 0; it < NPTS / 128; ++it) {
        const float4 ca0 = a0, cb0 = b0, ca1 = a1, cb1 = b1;
        a0 = p[0];  b0 = p[1];       // final-iter overrun lands in the pad
        a1 = p[64]; b1 = p[65];
        p += 128;

        // chunk-pair A: points (nb+lane, nb+32+lane)
        const unsigned long long dotA =
            add2(add2(mul2(qxp, pk2(ca0.x, ca0.y)),   // (x0,x1) aligned pair
                      mul2(qyp, pk2(ca0.z, ca0.w))),  // (y0,y1)
                 mul2(qzp, pk2(cb0.x, cb0.y)));       // (z0,z1)
        const unsigned long long d2A =
            add2(add2(qwp, pk2(cb0.z, cb0.w)), mul2(dotA, M2));  // (w0,w1)
        float d20, d21;
        upk2(d2A, d20, d21);

        // chunk-pair B: points (nb+64+lane, nb+96+lane)
        const unsigned long long dotB =
            add2(add2(mul2(qxp, pk2(ca1.x, ca1.y)),
                      mul2(qyp, pk2(ca1.z, ca1.w))),
                 mul2(qzp, pk2(cb1.x, cb1.y)));
        const unsigned long long d2B =
            add2(add2(qwp, pk2(cb1.z, cb1.w)), mul2(dotB, M2));
        float d22, d23;
        upk2(d2B, d22, d23);

        const bool h0 = d20 < r2;
        const bool h1 = d21 < r2;
        const bool h2 = d22 < r2;
        const bool h3 = d23 < r2;
        const unsigned bal0 = __ballot_sync(0xffffffffu, h0);
        const unsigned bal1 = __ballot_sync(0xffffffffu, h1);
        const unsigned bal2 = __ballot_sync(0xffffffffu, h2);
        const unsigned bal3 = __ballot_sync(0xffffffffu, h3);

        if (h0) scr[w][count + __popc(bal0 & mlt)] = f0;
        int cn = count + __popc(bal0);
        if (h1) scr[w][cn + __popc(bal1 & mlt)] = f1;
        cn += __popc(bal1);
        if (h2) scr[w][cn + __popc(bal2 & mlt)] = f2;
        cn += __popc(bal2);
        if (h3) scr[w][cn + __popc(bal3 & mlt)] = f3;
        count = cn + __popc(bal3);

        f0 += 128.0f;
        f1 += 128.0f;
        f2 += 128.0f;
        f3 += 128.0f;

        if (count >= NSAMPLE) break;  // count is warp-uniform
    }

    __syncwarp();                     // order scratch stores within the warp
    const int sel = (lane < count) ? lane : 0;  // scr[0] == smallest hit
    out[(size_t)gw * NSAMPLE + lane] = scr[w][sel];
}

extern "C" void kernel_launch(void* const* d_in, const int* in_sizes, int n_in,
                              void* d_out, int out_size) {
    const float* xyz = (const float*)d_in[0];  // 'xyz' (B, N, 3) float32
    // d_in[1] ('xyz_new') is unused by the reference (it queries xyz vs xyz).
    const int B = in_sizes[0] / (NPTS * 3);    // 8
    float* out = (float*)d_out;

    const int total_recs = B * RECS_PER_B;     // 16384
    pack_kernel<<<(total_recs + 255) / 256, 256>>>(xyz, total_recs);

    const int blocks = (B * NPTS) / WARPS_PER_BLOCK;  // 16384
    ball_query_kernel<<<blocks, BLOCK_THREADS>>>(xyz, out);
}

// round 14
// speedup vs baseline: 1.4616x; 1.4616x over previous
#include <cuda_runtime.h>
#include <cuda_bf16.h>

#define NSAMPLE 32
#define NPTS 4096
#define MAXB 8
#define BLOCK_THREADS 64
#define WARPS_PER_BLOCK (BLOCK_THREADS / 32)
#define SCR_SLOTS 192            // max slot overshoot: 31 + 128 = 159

// Layout: per 64-point chunk-pair cp (points n0 = cp*64+l, n1 = n0+32,
// l = 0..31), 64 contiguous float4s:
//   [cp*64 + l]      = A = (x_n0, x_n1, y_n0, y_n1)
//   [cp*64 + 32 + l] = B = (z_n0, z_n1, w_n0, w_n1)
// Lanes are 16B-contiguous inside each 512B record block -> every LDG.128 is
// 4 L1 wavefronts, exactly like R12 (R13's 32B lane stride doubled this).
// Each float4 lands (x0,x1)/(y0,y1) in adjacent even-aligned registers, so
// the pk2 movs fold away. +128 pad for final-iteration prefetch overrun.
__device__ float4 g_pk[MAXB * NPTS + 128];

// ---- f32x2 helpers (sm_103a); arithmetic FROZEN from rounds 10/12
// (rel_err 7.915904e-4 with seed-deterministic inputs).
__device__ __forceinline__ unsigned long long pk2(float lo, float hi) {
    unsigned long long r;
    asm("mov.b64 %0, {%1, %2};" : "=l"(r) : "f"(lo), "f"(hi));
    return r;
}
__device__ __forceinline__ void upk2(unsigned long long v, float& lo, float& hi) {
    asm("mov.b64 {%0, %1}, %2;" : "=f"(lo), "=f"(hi) : "l"(v));
}
__device__ __forceinline__ unsigned long long mul2(unsigned long long a,
                                                   unsigned long long b) {
    unsigned long long r;
    asm("mul.rn.f32x2 %0, %1, %2;" : "=l"(r) : "l"(a), "l"(b));
    return r;
}
__device__ __forceinline__ unsigned long long add2(unsigned long long a,
                                                   unsigned long long b) {
    unsigned long long r;
    asm("add.rn.f32x2 %0, %1, %2;" : "=l"(r) : "l"(a), "l"(b));
    return r;
}

// Pre-pass: one thread per point-pair. |p|^2 expression FROZEN:
// rn((rn(x*x) + rn(y*y)) + rn(z*z)), no FMA contraction.
__global__ void pack_kernel(const float* __restrict__ xyz, int total_pairs) {
    const int j = blockIdx.x * blockDim.x + threadIdx.x;
    if (j >= total_pairs) return;
    const int b = j / (NPTS / 2);
    const int s = j - b * (NPTS / 2);
    const int cp = s >> 5;           // chunk-pair within batch
    const int l = s & 31;
    const int n0 = b * NPTS + cp * 64 + l;
    const int n1 = n0 + 32;

    const float x0 = xyz[n0 * 3 + 0], y0 = xyz[n0 * 3 + 1], z0 = xyz[n0 * 3 + 2];
    const float x1 = xyz[n1 * 3 + 0], y1 = xyz[n1 * 3 + 1], z1 = xyz[n1 * 3 + 2];
    const float w0 = __fadd_rn(__fadd_rn(__fmul_rn(x0, x0), __fmul_rn(y0, y0)),
                               __fmul_rn(z0, z0));
    const float w1 = __fadd_rn(__fadd_rn(__fmul_rn(x1, x1), __fmul_rn(y1, y1)),
                               __fmul_rn(z1, z1));
    const int base = (b * (NPTS / 64) + cp) * 64;
    g_pk[base + l]      = make_float4(x0, x1, y0, y1);  // A record
    g_pk[base + 32 + l] = make_float4(z0, z1, w0, w1);  // B record
}

// One warp per query, 128 points/iter: R12's skeleton VERBATIM (same single
// pointer, same offsets, same copy-then-prefetch float4 regs) — only the
// meaning of the loaded float4s changed, eliminating the operand-packing
// movs. All f32x2 ops bit-identical to rounds 10/12. Ballot-ordered deferred
// smem emission; epilogue select = copy + truncate + pad-with-first.
__global__ void ball_query_kernel(const float* __restrict__ xyz,
                                  float* __restrict__ out) {
    __shared__ float scr[WARPS_PER_BLOCK][SCR_SLOTS];

    const int lane = threadIdx.x & 31;
    const int w = threadIdx.x >> 5;
    const int gw = blockIdx.x * WARPS_PER_BLOCK + w;
    const int b = gw >> 12;          // / NPTS

    const float4* __restrict__ p = g_pk + (size_t)b * NPTS;

    // Query from xyz; qw uses the frozen |q|^2 expression.
    const float qx = xyz[gw * 3 + 0];
    const float qy = xyz[gw * 3 + 1];
    const float qz = xyz[gw * 3 + 2];
    const float qw = __fadd_rn(__fadd_rn(__fmul_rn(qx, qx), __fmul_rn(qy, qy)),
                               __fmul_rn(qz, qz));
    const unsigned long long qxp = pk2(qx, qx);
    const unsigned long long qyp = pk2(qy, qy);
    const unsigned long long qzp = pk2(qz, qz);
    const unsigned long long qwp = pk2(qw, qw);
    const unsigned long long M2  = pk2(-2.0f, -2.0f);

    const unsigned mlt = (1u << lane) - 1u;
    const float r2 = 0.04f;          // f32 promotion of 0.2*0.2
    int count = 0;

    // Prefetch iteration 0 (2 chunk-pairs = 128 points), R12 offsets.
    float4 s0 = p[lane];             // A of pair 0: (x,x,y,y) for (l, l+32)
    float4 s1 = p[32 + lane];        // B of pair 0: (z,z,w,w)
    float4 s2 = p[64 + lane];        // A of pair 1
    float4 s3 = p[96 + lane];        // B of pair 1
    p += 128;

    float f0 = (float)lane;          // emission values, +128.0f per iter
    float f1 = (float)(lane + 32);
    float f2 = (float)(lane + 64);
    float f3 = (float)(lane + 96);

    for (int it = 0; it < NPTS / 128; ++it) {
        const float4 a0 = s0, b0 = s1, a1 = s2, b1 = s3;
        s0 = p[lane];                // final-iter overrun lands in the pad
        s1 = p[32 + lane];
        s2 = p[64 + lane];
        s3 = p[96 + lane];
        p += 128;

        // pair 0: points (nb+lane, nb+32+lane); operand pairs already
        // register-adjacent -> pk2 folds to register aliasing.
        const unsigned long long dotA =
            add2(add2(mul2(qxp, pk2(a0.x, a0.y)),
                      mul2(qyp, pk2(a0.z, a0.w))),
                 mul2(qzp, pk2(b0.x, b0.y)));
        const unsigned long long d2A =
            add2(add2(qwp, pk2(b0.z, b0.w)), mul2(dotA, M2));
        float d20, d21;
        upk2(d2A, d20, d21);

        // pair 1: points (nb+64+lane, nb+96+lane)
        const unsigned long long dotB =
            add2(add2(mul2(qxp, pk2(a1.x, a1.y)),
                      mul2(qyp, pk2(a1.z, a1.w))),
                 mul2(qzp, pk2(b1.x, b1.y)));
        const unsigned long long d2B =
            add2(add2(qwp, pk2(b1.z, b1.w)), mul2(dotB, M2));
        float d22, d23;
        upk2(d2B, d22, d23);

        const bool h0 = d20 < r2;
        const bool h1 = d21 < r2;
        const bool h2 = d22 < r2;
        const bool h3 = d23 < r2;
        const unsigned bal0 = __ballot_sync(0xffffffffu, h0);
        const unsigned bal1 = __ballot_sync(0xffffffffu, h1);
        const unsigned bal2 = __ballot_sync(0xffffffffu, h2);
        const unsigned bal3 = __ballot_sync(0xffffffffu, h3);

        if (h0) scr[w][count + __popc(bal0 & mlt)] = f0;
        int cn = count + __popc(bal0);
        if (h1) scr[w][cn + __popc(bal1 & mlt)] = f1;
        cn += __popc(bal1);
        if (h2) scr[w][cn + __popc(bal2 & mlt)] = f2;
        cn += __popc(bal2);
        if (h3) scr[w][cn + __popc(bal3 & mlt)] = f3;
        count = cn + __popc(bal3);

        f0 += 128.0f;
        f1 += 128.0f;
        f2 += 128.0f;
        f3 += 128.0f;

        if (count >= NSAMPLE) break;  // count is warp-uniform
    }

    __syncwarp();                     // order scratch stores within the warp
    const int sel = (lane < count) ? lane : 0;  // scr[0] == smallest hit
    out[(size_t)gw * NSAMPLE + lane] = scr[w][sel];
}

extern "C" void kernel_launch(void* const* d_in, const int* in_sizes, int n_in,
                              void* d_out, int out_size) {
    const float* xyz = (const float*)d_in[0];  // 'xyz' (B, N, 3) float32
    // d_in[1] ('xyz_new') is unused by the reference (it queries xyz vs xyz).
    const int B = in_sizes[0] / (NPTS * 3);    // 8
    float* out = (float*)d_out;

    const int total_pairs = B * (NPTS / 2);    // 16384
    pack_kernel<<<(total_pairs + 255) / 256, 256>>>(xyz, total_pairs);

    const int blocks = (B * NPTS) / WARPS_PER_BLOCK;  // 16384
    ball_query_kernel<<<blocks, BLOCK_THREADS>>>(xyz, out);
}